// round 9
// baseline (speedup 1.0000x reference)
#include <cuda_runtime.h>

// ---------------------------------------------------------------------------
// GTN forward, round 9.
//   memset  : g_nnz = 0 (cudaMemsetAsync, graph-capturable)
//   k_scan  : blocks [0,256):   XW = X @ Wg (32x64 tiles)
//             blocks [256,1280): streaming sparsify of A — 16 independent
//               __ldcs loads/thread (launch_bounds(256,2) keeps them live),
//               warp-aggregated slot assignment (1 atomic/warp/quad)
//   k_y     : Y[c] = A2[c] @ XW (unroll-8 sparse gather)
//   k_final : dense smem H row + touched-column list; atomicExch dedupe for
//             threshold/degree/drops; out = relu(coef*(A1.Y - corr) + bg)
// ---------------------------------------------------------------------------

#define NN 2048
#define NE 4
#define NC 2
#define WIN 512
#define WOUT 256
#define CAP 128
#define MAXDROP 128
#define TCAP 640
#define THRESH 0.05f
#define WEPS 1e-4f

#define PLANE4 ((size_t)NN * NN / 4)    // float4 per plane = 1048576
#define QUART4 (PLANE4 / 4)             // 262144
#define SCAN_BLOCKS 1024                // 1024*256 = QUART4 threads
#define GEMM_BLOCKS 256                 // (2048/32)*(256/64)

// Scratch (device globals; no allocations allowed)
__device__ int    g_nnz[NN];
__device__ int    g_cols[NN * CAP];
__device__ float4 g_a12[NN * CAP];      // (a1c0, a1c1, a2c0, a2c1)
__device__ float  g_XW[NN * WOUT];
__device__ float  g_Y[NC][NN * WOUT];

// ---------------------------------------------------------------- k_scan
__device__ __forceinline__ void scan_emit(int i, int j, int slot,
                                          float a0, float a1, float a2, float a3,
                                          const float4& f1a, const float4& f1b,
                                          const float4& f2a, const float4& f2b) {
    if (slot < CAP) {
        int idx = i * CAP + slot;
        g_cols[idx] = j;
        g_a12[idx] = make_float4(
            f1a.x * a0 + f1a.y * a1 + f1a.z * a2 + f1a.w * a3,
            f1b.x * a0 + f1b.y * a1 + f1b.z * a2 + f1b.w * a3,
            f2a.x * a0 + f2a.y * a1 + f2a.z * a2 + f2a.w * a3,
            f2b.x * a0 + f2b.y * a1 + f2b.z * a2 + f2b.w * a3);
    }
}

__global__ void __launch_bounds__(256, 2)
k_scan(const float* __restrict__ A,
       const float* __restrict__ X,
       const float* __restrict__ Wg,
       const float* __restrict__ W1a,
       const float* __restrict__ W1b) {
    __shared__ float As[16][33];
    __shared__ float Bs[16][64];
    __shared__ float4 sf[4];            // f1 c0, f1 c1, f2 c0, f2 c1
    const int tid = threadIdx.x;

    if (blockIdx.x < GEMM_BLOCKS) {
        // -------------------------------------- GEMM role: XW = X @ Wg
        const int b  = blockIdx.x;
        const int bm = (b >> 2) * 32;
        const int bn = (b & 3) * 64;
        const int tx = tid & 15;
        const int ty = tid >> 4;
        float acc[2][4] = {};

        for (int k0 = 0; k0 < WIN; k0 += 16) {
            #pragma unroll
            for (int t = 0; t < 2; t++) {
                int idx = tid + t * 256;
                int kk = idx & 15, m = idx >> 4;
                As[kk][m] = X[(size_t)(bm + m) * WIN + k0 + kk];
            }
            #pragma unroll
            for (int t = 0; t < 4; t++) {
                int idx = tid + t * 256;
                int n = idx & 63, kk = idx >> 6;
                Bs[kk][n] = Wg[(size_t)(k0 + kk) * WOUT + bn + n];
            }
            __syncthreads();
            #pragma unroll
            for (int k = 0; k < 16; k++) {
                float a0 = As[k][ty * 2 + 0];
                float a1 = As[k][ty * 2 + 1];
                float4 b4 = *(const float4*)&Bs[k][tx * 4];
                acc[0][0] = fmaf(a0, b4.x, acc[0][0]);
                acc[0][1] = fmaf(a0, b4.y, acc[0][1]);
                acc[0][2] = fmaf(a0, b4.z, acc[0][2]);
                acc[0][3] = fmaf(a0, b4.w, acc[0][3]);
                acc[1][0] = fmaf(a1, b4.x, acc[1][0]);
                acc[1][1] = fmaf(a1, b4.y, acc[1][1]);
                acc[1][2] = fmaf(a1, b4.z, acc[1][2]);
                acc[1][3] = fmaf(a1, b4.w, acc[1][3]);
            }
            __syncthreads();
        }
        #pragma unroll
        for (int u = 0; u < 2; u++) {
            float4 o = make_float4(acc[u][0], acc[u][1], acc[u][2], acc[u][3]);
            *(float4*)&g_XW[(size_t)(bm + ty * 2 + u) * WOUT + bn + tx * 4] = o;
        }
        return;
    }

    // ------------------------------------------ scan role
    if (tid == 0) {
        // softmax over edge dim (per block; deterministic, cheap)
        const float* Ws[2] = {W1a, W1b};
        for (int w = 0; w < 2; w++) {
            for (int c = 0; c < NC; c++) {
                float m = -1e30f;
                for (int e = 0; e < NE; e++) m = fmaxf(m, Ws[w][c * NE + e]);
                float ex[NE], s = 0.f;
                for (int e = 0; e < NE; e++) { ex[e] = expf(Ws[w][c * NE + e] - m); s += ex[e]; }
                float f[NE];
                for (int e = 0; e < NE; e++) {
                    float v = ex[e] / s;
                    f[e] = (v < WEPS) ? 0.f : v;
                }
                sf[w * 2 + c] = make_float4(f[0], f[1], f[2], f[3]);
            }
        }
    }
    __syncthreads();
    const float4 f1a = sf[0], f1b = sf[1], f2a = sf[2], f2b = sf[3];

    const size_t t = (size_t)(blockIdx.x - GEMM_BLOCKS) * 256 + tid;
    const float4* base = (const float4*)A;
    const int lane = tid & 31;
    const unsigned mlt = (1u << lane) - 1u;

    // 16 fully independent streaming loads in one batch
    float4 v[4][4];
    #pragma unroll
    for (int q = 0; q < 4; q++) {
        size_t p = t + (size_t)q * QUART4;
        #pragma unroll
        for (int e = 0; e < 4; e++)
            v[q][e] = __ldcs(base + p + (size_t)e * PLANE4);
    }

    #pragma unroll
    for (int q = 0; q < 4; q++) {
        float c0[4] = {v[q][0].x, v[q][1].x, v[q][2].x, v[q][3].x};
        float c1[4] = {v[q][0].y, v[q][1].y, v[q][2].y, v[q][3].y};
        float c2[4] = {v[q][0].z, v[q][1].z, v[q][2].z, v[q][3].z};
        float c3[4] = {v[q][0].w, v[q][1].w, v[q][2].w, v[q][3].w};
        bool nz0 = (c0[0] != 0.f) | (c0[1] != 0.f) | (c0[2] != 0.f) | (c0[3] != 0.f);
        bool nz1 = (c1[0] != 0.f) | (c1[1] != 0.f) | (c1[2] != 0.f) | (c1[3] != 0.f);
        bool nz2 = (c2[0] != 0.f) | (c2[1] != 0.f) | (c2[2] != 0.f) | (c2[3] != 0.f);
        bool nz3 = (c3[0] != 0.f) | (c3[1] != 0.f) | (c3[2] != 0.f) | (c3[3] != 0.f);
        unsigned b0 = __ballot_sync(0xffffffffu, nz0);
        unsigned b1 = __ballot_sync(0xffffffffu, nz1);
        unsigned b2 = __ballot_sync(0xffffffffu, nz2);
        unsigned b3 = __ballot_sync(0xffffffffu, nz3);
        int tot = __popc(b0) + __popc(b1) + __popc(b2) + __popc(b3);
        if (tot == 0) continue;                 // warp-uniform

        size_t p = t + (size_t)q * QUART4;
        int i = (int)(p >> 9);                  // whole warp: same row
        int j0 = ((int)p & 511) * 4;
        int base_slot = 0;
        if (lane == 0) base_slot = atomicAdd(&g_nnz[i], tot);
        base_slot = __shfl_sync(0xffffffffu, base_slot, 0);

        int o = base_slot;
        if (nz0) scan_emit(i, j0 + 0, o + __popc(b0 & mlt), c0[0], c0[1], c0[2], c0[3], f1a, f1b, f2a, f2b);
        o += __popc(b0);
        if (nz1) scan_emit(i, j0 + 1, o + __popc(b1 & mlt), c1[0], c1[1], c1[2], c1[3], f1a, f1b, f2a, f2b);
        o += __popc(b1);
        if (nz2) scan_emit(i, j0 + 2, o + __popc(b2 & mlt), c2[0], c2[1], c2[2], c2[3], f1a, f1b, f2a, f2b);
        o += __popc(b2);
        if (nz3) scan_emit(i, j0 + 3, o + __popc(b3 & mlt), c3[0], c3[1], c3[2], c3[3], f1a, f1b, f2a, f2b);
    }
}

// ---------------------------------------------------------------- k_y
__global__ void __launch_bounds__(256) k_y() {
    const int k = blockIdx.x;
    const int f = threadIdx.x;
    __shared__ int   scol[CAP];
    __shared__ float sv0[CAP], sv1[CAP];
    const int n2 = min(g_nnz[k], CAP);
    for (int s = f; s < n2; s += 256) {
        int idx = k * CAP + s;
        scol[s] = g_cols[idx] * WOUT;
        float4 a = g_a12[idx];
        sv0[s] = a.z;
        sv1[s] = a.w;
    }
    __syncthreads();
    float acc0 = 0.f, acc1 = 0.f;
    int s = 0;
    for (; s + 8 <= n2; s += 8) {
        float x[8];
        #pragma unroll
        for (int u = 0; u < 8; u++) x[u] = __ldg(&g_XW[scol[s + u] + f]);
        #pragma unroll
        for (int u = 0; u < 8; u++) {
            acc0 = fmaf(sv0[s + u], x[u], acc0);
            acc1 = fmaf(sv1[s + u], x[u], acc1);
        }
    }
    for (; s + 4 <= n2; s += 4) {
        float x[4];
        #pragma unroll
        for (int u = 0; u < 4; u++) x[u] = __ldg(&g_XW[scol[s + u] + f]);
        #pragma unroll
        for (int u = 0; u < 4; u++) {
            acc0 = fmaf(sv0[s + u], x[u], acc0);
            acc1 = fmaf(sv1[s + u], x[u], acc1);
        }
    }
    for (; s < n2; s++) {
        float x = __ldg(&g_XW[scol[s] + f]);
        acc0 = fmaf(sv0[s], x, acc0);
        acc1 = fmaf(sv1[s], x, acc1);
    }
    g_Y[0][(size_t)k * WOUT + f] = acc0;
    g_Y[1][(size_t)k * WOUT + f] = acc1;
}

// ---------------------------------------------------------------- k_final
__global__ void __launch_bounds__(256) k_final(const float* __restrict__ bg,
                                               float* __restrict__ out) {
    const int i = blockIdx.x;
    const int tid = threadIdx.x;
    const int warp = tid >> 5, lane = tid & 31;

    __shared__ float H0[NN], H1[NN];
    __shared__ int   offs[CAP];          // c1*WOUT
    __shared__ int   n2s[CAP];           // prefetched neighbor nnz
    __shared__ float w0s[CAP], w1s[CAP];
    __shared__ int   tj[TCAP];           // touched columns (with dups)
    __shared__ int   tcnt;
    __shared__ float degsh[NC];
    __shared__ int   dropn[NC];
    __shared__ int   dropj[NC][MAXDROP];
    __shared__ float droph[NC][MAXDROP];

    float4 z = make_float4(0.f, 0.f, 0.f, 0.f);
    for (int t = tid; t < NN / 4; t += 256) {
        ((float4*)H0)[t] = z;
        ((float4*)H1)[t] = z;
    }
    if (tid < NC) { degsh[tid] = 0.f; dropn[tid] = 0; }
    if (tid == 0) tcnt = 0;
    const int n1 = min(g_nnz[i], CAP);
    for (int s = tid; s < n1; s += 256) {
        int idx = i * CAP + s;
        int c = g_cols[idx];
        offs[s] = c * WOUT;
        n2s[s] = min(g_nnz[c], CAP);
        float4 a = g_a12[idx];
        w0s[s] = a.x;
        w1s[s] = a.y;
    }
    __syncthreads();

    // scatter: one warp per source slot s, lanes over target slots s2.
    // Also append touched column to tj (dups fine, dedupe below).
    for (int s = warp; s < n1; s += 8) {
        int kbase = (offs[s] / WOUT) * CAP;
        int n2 = n2s[s];
        float w0 = w0s[s], w1 = w1s[s];
        for (int s2 = lane; s2 < n2; s2 += 32) {
            int idx = kbase + s2;
            int j = g_cols[idx];
            float4 a = g_a12[idx];
            float h0 = w0 * a.z;
            float h1 = w1 * a.w;
            if (h0 != 0.f) atomicAdd(&H0[j], h0);
            if (h1 != 0.f) atomicAdd(&H1[j], h1);
            int p = atomicAdd(&tcnt, 1);
            if (p < TCAP) tj[p] = j;
        }
    }
    __syncthreads();

    const int tc = tcnt;
    if (tc <= TCAP) {
        // dedupe + threshold via atomicExch over touched list only
        for (int u = tid; u < tc; u += 256) {
            int j = tj[u];
            float h0 = atomicExch(&H0[j], 0.f);
            float h1 = atomicExch(&H1[j], 0.f);
            if (h0 > THRESH) atomicAdd(&degsh[0], h0);
            else if (h0 > 0.f) {
                int p = atomicAdd(&dropn[0], 1);
                if (p < MAXDROP) { dropj[0][p] = j; droph[0][p] = h0; }
            }
            if (h1 > THRESH) atomicAdd(&degsh[1], h1);
            else if (h1 > 0.f) {
                int p = atomicAdd(&dropn[1], 1);
                if (p < MAXDROP) { dropj[1][p] = j; droph[1][p] = h1; }
            }
        }
    } else {
        // fallback: full scan (deterministic — tc depends only on structure)
        float d0 = 0.f, d1 = 0.f;
        for (int j = tid; j < NN; j += 256) {
            float h0 = H0[j];
            if (h0 > THRESH) d0 += h0;
            else if (h0 > 0.f) {
                int p = atomicAdd(&dropn[0], 1);
                if (p < MAXDROP) { dropj[0][p] = j; droph[0][p] = h0; }
            }
            float h1 = H1[j];
            if (h1 > THRESH) d1 += h1;
            else if (h1 > 0.f) {
                int p = atomicAdd(&dropn[1], 1);
                if (p < MAXDROP) { dropj[1][p] = j; droph[1][p] = h1; }
            }
        }
        #pragma unroll
        for (int o = 16; o > 0; o >>= 1) {
            d0 += __shfl_down_sync(0xffffffff, d0, o);
            d1 += __shfl_down_sync(0xffffffff, d1, o);
        }
        if (lane == 0) {
            if (d0 != 0.f) atomicAdd(&degsh[0], d0);
            if (d1 != 0.f) atomicAdd(&degsh[1], d1);
        }
    }
    __syncthreads();

    float coef[NC];
    #pragma unroll
    for (int c = 0; c < NC; c++) {
        float deg = degsh[c];
        if (deg > 0.f) {
            float dinv = 1.f / deg;
            float deg2 = deg * dinv;     // double row-normalization
            coef[c] = dinv * (1.f / deg2);
        } else {
            coef[c] = 0.f;
        }
    }

    // output: feature f = tid; interleave channel gathers (8 loads in flight)
    const int f = tid;
    const float bias = bg[f];
    const float* Y0 = g_Y[0];
    const float* Y1 = g_Y[1];
    float acc0 = 0.f, acc1 = 0.f;
    int s = 0;
    for (; s + 4 <= n1; s += 4) {
        int o0 = offs[s + 0] + f, o1 = offs[s + 1] + f;
        int o2 = offs[s + 2] + f, o3 = offs[s + 3] + f;
        float a0 = __ldg(Y0 + o0), b0 = __ldg(Y1 + o0);
        float a1 = __ldg(Y0 + o1), b1 = __ldg(Y1 + o1);
        float a2 = __ldg(Y0 + o2), b2 = __ldg(Y1 + o2);
        float a3 = __ldg(Y0 + o3), b3 = __ldg(Y1 + o3);
        acc0 = fmaf(w0s[s + 0], a0, acc0); acc1 = fmaf(w1s[s + 0], b0, acc1);
        acc0 = fmaf(w0s[s + 1], a1, acc0); acc1 = fmaf(w1s[s + 1], b1, acc1);
        acc0 = fmaf(w0s[s + 2], a2, acc0); acc1 = fmaf(w1s[s + 2], b2, acc1);
        acc0 = fmaf(w0s[s + 3], a3, acc0); acc1 = fmaf(w1s[s + 3], b3, acc1);
    }
    for (; s < n1; s++) {
        int o = offs[s] + f;
        acc0 = fmaf(w0s[s], __ldg(Y0 + o), acc0);
        acc1 = fmaf(w1s[s], __ldg(Y1 + o), acc1);
    }

    int nd0 = min(dropn[0], MAXDROP);
    for (int d = 0; d < nd0; d++)
        acc0 -= droph[0][d] * g_XW[(size_t)dropj[0][d] * WOUT + f];
    int nd1 = min(dropn[1], MAXDROP);
    for (int d = 0; d < nd1; d++)
        acc1 -= droph[1][d] * g_XW[(size_t)dropj[1][d] * WOUT + f];

    float o0 = coef[0] * acc0 + bias;
    float o1 = coef[1] * acc1 + bias;
    out[(size_t)i * (NC * WOUT) + f]        = fmaxf(o0, 0.f);
    out[(size_t)i * (NC * WOUT) + WOUT + f] = fmaxf(o1, 0.f);
}

// ---------------------------------------------------------------------------
extern "C" void kernel_launch(void* const* d_in, const int* in_sizes, int n_in,
                              void* d_out, int out_size) {
    const float* A   = (const float*)d_in[0];
    const float* X   = (const float*)d_in[1];
    const float* W1a = (const float*)d_in[2];
    const float* W1b = (const float*)d_in[3];
    const float* Wg  = (const float*)d_in[4];
    const float* bg  = (const float*)d_in[5];
    float* out = (float*)d_out;

    void* nnz_ptr = nullptr;
    cudaGetSymbolAddress(&nnz_ptr, g_nnz);
    cudaMemsetAsync(nnz_ptr, 0, NN * sizeof(int));

    k_scan<<<GEMM_BLOCKS + SCAN_BLOCKS, 256>>>(A, X, Wg, W1a, W1b);
    k_y<<<NN, 256>>>();
    k_final<<<NN, 256>>>(bg, out);
}

// round 10
// speedup vs baseline: 1.0053x; 1.0053x over previous
#include <cuda_runtime.h>

// ---------------------------------------------------------------------------
// GTN forward, round 10.
//   memset : g_nnz = 0
//   k_pre  : blocks [0,256): XW = X @ Wg (32x64 tiles); blocks [256,264):
//            softmax edge weights -> g_f
//   k_scan : SEPARATE streaming sparsify (low-reg, high-occupancy):
//            8 independent __ldcs float4 loads/thread, pre-ballot skip,
//            warp-aggregated slot atomics
//   k_y    : Y[c] = A2[c] @ XW (unroll-8 sparse gather)
//   k_final: dense smem H row + touched-column list (atomicExch dedupe),
//            out = relu(coef*(A1.Y - dropped corrections) + bg)
// ---------------------------------------------------------------------------

#define NN 2048
#define NE 4
#define NC 2
#define WIN 512
#define WOUT 256
#define CAP 128
#define MAXDROP 128
#define TCAP 640
#define THRESH 0.05f
#define WEPS 1e-4f

#define PLANE4 ((size_t)NN * NN / 4)    // float4 per plane = 1048576
#define HALF4  (PLANE4 / 2)             // 524288
#define SCAN_BLOCKS 2048                // 2048*256 = HALF4 threads
#define GEMM_BLOCKS 256                 // (2048/32)*(256/64)

// Scratch (device globals; no allocations allowed)
__device__ float4 g_f[4];               // f1c0, f1c1, f2c0, f2c1
__device__ int    g_nnz[NN];
__device__ int    g_cols[NN * CAP];
__device__ float4 g_a12[NN * CAP];      // (a1c0, a1c1, a2c0, a2c1)
__device__ float  g_XW[NN * WOUT];
__device__ float  g_Y[NC][NN * WOUT];

// ---------------------------------------------------------------- k_pre
__global__ void __launch_bounds__(256) k_pre(const float* __restrict__ X,
                                             const float* __restrict__ Wg,
                                             const float* __restrict__ W1a,
                                             const float* __restrict__ W1b) {
    __shared__ float As[16][33];
    __shared__ float Bs[16][64];
    const int tid = threadIdx.x;

    if (blockIdx.x >= GEMM_BLOCKS) {
        if (blockIdx.x == GEMM_BLOCKS && tid == 0) {
            const float* Ws[2] = {W1a, W1b};
            for (int w = 0; w < 2; w++) {
                for (int c = 0; c < NC; c++) {
                    float m = -1e30f;
                    for (int e = 0; e < NE; e++) m = fmaxf(m, Ws[w][c * NE + e]);
                    float ex[NE], s = 0.f;
                    for (int e = 0; e < NE; e++) { ex[e] = expf(Ws[w][c * NE + e] - m); s += ex[e]; }
                    float f[NE];
                    for (int e = 0; e < NE; e++) {
                        float v = ex[e] / s;
                        f[e] = (v < WEPS) ? 0.f : v;
                    }
                    g_f[w * 2 + c] = make_float4(f[0], f[1], f[2], f[3]);
                }
            }
        }
        return;
    }

    // -------------------------------------- GEMM: XW = X @ Wg
    const int b  = blockIdx.x;
    const int bm = (b >> 2) * 32;
    const int bn = (b & 3) * 64;
    const int tx = tid & 15;
    const int ty = tid >> 4;
    float acc[2][4] = {};

    for (int k0 = 0; k0 < WIN; k0 += 16) {
        #pragma unroll
        for (int t = 0; t < 2; t++) {
            int idx = tid + t * 256;
            int kk = idx & 15, m = idx >> 4;
            As[kk][m] = X[(size_t)(bm + m) * WIN + k0 + kk];
        }
        #pragma unroll
        for (int t = 0; t < 4; t++) {
            int idx = tid + t * 256;
            int n = idx & 63, kk = idx >> 6;
            Bs[kk][n] = Wg[(size_t)(k0 + kk) * WOUT + bn + n];
        }
        __syncthreads();
        #pragma unroll
        for (int k = 0; k < 16; k++) {
            float a0 = As[k][ty * 2 + 0];
            float a1 = As[k][ty * 2 + 1];
            float4 b4 = *(const float4*)&Bs[k][tx * 4];
            acc[0][0] = fmaf(a0, b4.x, acc[0][0]);
            acc[0][1] = fmaf(a0, b4.y, acc[0][1]);
            acc[0][2] = fmaf(a0, b4.z, acc[0][2]);
            acc[0][3] = fmaf(a0, b4.w, acc[0][3]);
            acc[1][0] = fmaf(a1, b4.x, acc[1][0]);
            acc[1][1] = fmaf(a1, b4.y, acc[1][1]);
            acc[1][2] = fmaf(a1, b4.z, acc[1][2]);
            acc[1][3] = fmaf(a1, b4.w, acc[1][3]);
        }
        __syncthreads();
    }
    #pragma unroll
    for (int u = 0; u < 2; u++) {
        float4 o = make_float4(acc[u][0], acc[u][1], acc[u][2], acc[u][3]);
        *(float4*)&g_XW[(size_t)(bm + ty * 2 + u) * WOUT + bn + tx * 4] = o;
    }
}

// ---------------------------------------------------------------- k_scan
__device__ __forceinline__ void scan_emit(int i, int j, int slot,
                                          float a0, float a1, float a2, float a3,
                                          const float4& f1a, const float4& f1b,
                                          const float4& f2a, const float4& f2b) {
    if (slot < CAP) {
        int idx = i * CAP + slot;
        g_cols[idx] = j;
        g_a12[idx] = make_float4(
            f1a.x * a0 + f1a.y * a1 + f1a.z * a2 + f1a.w * a3,
            f1b.x * a0 + f1b.y * a1 + f1b.z * a2 + f1b.w * a3,
            f2a.x * a0 + f2a.y * a1 + f2a.z * a2 + f2a.w * a3,
            f2b.x * a0 + f2b.y * a1 + f2b.z * a2 + f2b.w * a3);
    }
}

__device__ __forceinline__ void scan_quad(size_t p, const float4* v,
                                          int lane, unsigned mlt,
                                          const float4& f1a, const float4& f1b,
                                          const float4& f2a, const float4& f2b) {
    bool anynz = (v[0].x != 0.f) | (v[0].y != 0.f) | (v[0].z != 0.f) | (v[0].w != 0.f) |
                 (v[1].x != 0.f) | (v[1].y != 0.f) | (v[1].z != 0.f) | (v[1].w != 0.f) |
                 (v[2].x != 0.f) | (v[2].y != 0.f) | (v[2].z != 0.f) | (v[2].w != 0.f) |
                 (v[3].x != 0.f) | (v[3].y != 0.f) | (v[3].z != 0.f) | (v[3].w != 0.f);
    if (__ballot_sync(0xffffffffu, anynz) == 0u) return;   // warp-uniform skip

    bool nz0 = (v[0].x != 0.f) | (v[1].x != 0.f) | (v[2].x != 0.f) | (v[3].x != 0.f);
    bool nz1 = (v[0].y != 0.f) | (v[1].y != 0.f) | (v[2].y != 0.f) | (v[3].y != 0.f);
    bool nz2 = (v[0].z != 0.f) | (v[1].z != 0.f) | (v[2].z != 0.f) | (v[3].z != 0.f);
    bool nz3 = (v[0].w != 0.f) | (v[1].w != 0.f) | (v[2].w != 0.f) | (v[3].w != 0.f);
    unsigned b0 = __ballot_sync(0xffffffffu, nz0);
    unsigned b1 = __ballot_sync(0xffffffffu, nz1);
    unsigned b2 = __ballot_sync(0xffffffffu, nz2);
    unsigned b3 = __ballot_sync(0xffffffffu, nz3);
    int tot = __popc(b0) + __popc(b1) + __popc(b2) + __popc(b3);

    int i = (int)(p >> 9);                  // 512 float4 per row; warp: same row
    int j0 = ((int)p & 511) * 4;
    int base_slot = 0;
    if (lane == 0) base_slot = atomicAdd(&g_nnz[i], tot);
    base_slot = __shfl_sync(0xffffffffu, base_slot, 0);

    int o = base_slot;
    if (nz0) scan_emit(i, j0 + 0, o + __popc(b0 & mlt), v[0].x, v[1].x, v[2].x, v[3].x, f1a, f1b, f2a, f2b);
    o += __popc(b0);
    if (nz1) scan_emit(i, j0 + 1, o + __popc(b1 & mlt), v[0].y, v[1].y, v[2].y, v[3].y, f1a, f1b, f2a, f2b);
    o += __popc(b1);
    if (nz2) scan_emit(i, j0 + 2, o + __popc(b2 & mlt), v[0].z, v[1].z, v[2].z, v[3].z, f1a, f1b, f2a, f2b);
    o += __popc(b2);
    if (nz3) scan_emit(i, j0 + 3, o + __popc(b3 & mlt), v[0].w, v[1].w, v[2].w, v[3].w, f1a, f1b, f2a, f2b);
}

__global__ void __launch_bounds__(256) k_scan(const float* __restrict__ A) {
    const size_t t = (size_t)blockIdx.x * 256 + threadIdx.x;   // 0..HALF4-1
    const float4* base = (const float4*)A;
    const int lane = threadIdx.x & 31;
    const unsigned mlt = (1u << lane) - 1u;

    const float4 f1a = g_f[0], f1b = g_f[1], f2a = g_f[2], f2b = g_f[3];

    // 8 fully independent streaming loads in one batch (32 data regs)
    float4 v0[4], v1[4];
    #pragma unroll
    for (int e = 0; e < 4; e++) v0[e] = __ldcs(base + t + (size_t)e * PLANE4);
    #pragma unroll
    for (int e = 0; e < 4; e++) v1[e] = __ldcs(base + t + HALF4 + (size_t)e * PLANE4);

    scan_quad(t,         v0, lane, mlt, f1a, f1b, f2a, f2b);
    scan_quad(t + HALF4, v1, lane, mlt, f1a, f1b, f2a, f2b);
}

// ---------------------------------------------------------------- k_y
__global__ void __launch_bounds__(256) k_y() {
    const int k = blockIdx.x;
    const int f = threadIdx.x;
    __shared__ int   scol[CAP];
    __shared__ float sv0[CAP], sv1[CAP];
    const int n2 = min(g_nnz[k], CAP);
    for (int s = f; s < n2; s += 256) {
        int idx = k * CAP + s;
        scol[s] = g_cols[idx] * WOUT;
        float4 a = g_a12[idx];
        sv0[s] = a.z;
        sv1[s] = a.w;
    }
    __syncthreads();
    float acc0 = 0.f, acc1 = 0.f;
    int s = 0;
    for (; s + 8 <= n2; s += 8) {
        float x[8];
        #pragma unroll
        for (int u = 0; u < 8; u++) x[u] = __ldg(&g_XW[scol[s + u] + f]);
        #pragma unroll
        for (int u = 0; u < 8; u++) {
            acc0 = fmaf(sv0[s + u], x[u], acc0);
            acc1 = fmaf(sv1[s + u], x[u], acc1);
        }
    }
    for (; s + 4 <= n2; s += 4) {
        float x[4];
        #pragma unroll
        for (int u = 0; u < 4; u++) x[u] = __ldg(&g_XW[scol[s + u] + f]);
        #pragma unroll
        for (int u = 0; u < 4; u++) {
            acc0 = fmaf(sv0[s + u], x[u], acc0);
            acc1 = fmaf(sv1[s + u], x[u], acc1);
        }
    }
    for (; s < n2; s++) {
        float x = __ldg(&g_XW[scol[s] + f]);
        acc0 = fmaf(sv0[s], x, acc0);
        acc1 = fmaf(sv1[s], x, acc1);
    }
    g_Y[0][(size_t)k * WOUT + f] = acc0;
    g_Y[1][(size_t)k * WOUT + f] = acc1;
}

// ---------------------------------------------------------------- k_final
__global__ void __launch_bounds__(256) k_final(const float* __restrict__ bg,
                                               float* __restrict__ out) {
    const int i = blockIdx.x;
    const int tid = threadIdx.x;
    const int warp = tid >> 5, lane = tid & 31;

    __shared__ float H0[NN], H1[NN];
    __shared__ int   offs[CAP];
    __shared__ int   n2s[CAP];
    __shared__ float w0s[CAP], w1s[CAP];
    __shared__ int   tj[TCAP];
    __shared__ int   tcnt;
    __shared__ float degsh[NC];
    __shared__ int   dropn[NC];
    __shared__ int   dropj[NC][MAXDROP];
    __shared__ float droph[NC][MAXDROP];

    float4 z = make_float4(0.f, 0.f, 0.f, 0.f);
    for (int t = tid; t < NN / 4; t += 256) {
        ((float4*)H0)[t] = z;
        ((float4*)H1)[t] = z;
    }
    if (tid < NC) { degsh[tid] = 0.f; dropn[tid] = 0; }
    if (tid == 0) tcnt = 0;
    const int n1 = min(g_nnz[i], CAP);
    for (int s = tid; s < n1; s += 256) {
        int idx = i * CAP + s;
        int c = g_cols[idx];
        offs[s] = c * WOUT;
        n2s[s] = min(g_nnz[c], CAP);
        float4 a = g_a12[idx];
        w0s[s] = a.x;
        w1s[s] = a.y;
    }
    __syncthreads();

    // scatter: one warp per source slot s; also log touched columns
    for (int s = warp; s < n1; s += 8) {
        int kbase = (offs[s] / WOUT) * CAP;
        int n2 = n2s[s];
        float w0 = w0s[s], w1 = w1s[s];
        for (int s2 = lane; s2 < n2; s2 += 32) {
            int idx = kbase + s2;
            int j = g_cols[idx];
            float4 a = g_a12[idx];
            float h0 = w0 * a.z;
            float h1 = w1 * a.w;
            if (h0 != 0.f) atomicAdd(&H0[j], h0);
            if (h1 != 0.f) atomicAdd(&H1[j], h1);
            int p = atomicAdd(&tcnt, 1);
            if (p < TCAP) tj[p] = j;
        }
    }
    __syncthreads();

    const int tc = tcnt;
    if (tc <= TCAP) {
        for (int u = tid; u < tc; u += 256) {
            int j = tj[u];
            float h0 = atomicExch(&H0[j], 0.f);
            float h1 = atomicExch(&H1[j], 0.f);
            if (h0 > THRESH) atomicAdd(&degsh[0], h0);
            else if (h0 > 0.f) {
                int p = atomicAdd(&dropn[0], 1);
                if (p < MAXDROP) { dropj[0][p] = j; droph[0][p] = h0; }
            }
            if (h1 > THRESH) atomicAdd(&degsh[1], h1);
            else if (h1 > 0.f) {
                int p = atomicAdd(&dropn[1], 1);
                if (p < MAXDROP) { dropj[1][p] = j; droph[1][p] = h1; }
            }
        }
    } else {
        float d0 = 0.f, d1 = 0.f;
        for (int j = tid; j < NN; j += 256) {
            float h0 = H0[j];
            if (h0 > THRESH) d0 += h0;
            else if (h0 > 0.f) {
                int p = atomicAdd(&dropn[0], 1);
                if (p < MAXDROP) { dropj[0][p] = j; droph[0][p] = h0; }
            }
            float h1 = H1[j];
            if (h1 > THRESH) d1 += h1;
            else if (h1 > 0.f) {
                int p = atomicAdd(&dropn[1], 1);
                if (p < MAXDROP) { dropj[1][p] = j; droph[1][p] = h1; }
            }
        }
        #pragma unroll
        for (int o = 16; o > 0; o >>= 1) {
            d0 += __shfl_down_sync(0xffffffff, d0, o);
            d1 += __shfl_down_sync(0xffffffff, d1, o);
        }
        if (lane == 0) {
            if (d0 != 0.f) atomicAdd(&degsh[0], d0);
            if (d1 != 0.f) atomicAdd(&degsh[1], d1);
        }
    }
    __syncthreads();

    float coef[NC];
    #pragma unroll
    for (int c = 0; c < NC; c++) {
        float deg = degsh[c];
        if (deg > 0.f) {
            float dinv = 1.f / deg;
            float deg2 = deg * dinv;
            coef[c] = dinv * (1.f / deg2);
        } else {
            coef[c] = 0.f;
        }
    }

    const int f = tid;
    const float bias = bg[f];
    const float* Y0 = g_Y[0];
    const float* Y1 = g_Y[1];
    float acc0 = 0.f, acc1 = 0.f;
    int s = 0;
    for (; s + 4 <= n1; s += 4) {
        int o0 = offs[s + 0] + f, o1 = offs[s + 1] + f;
        int o2 = offs[s + 2] + f, o3 = offs[s + 3] + f;
        float a0 = __ldg(Y0 + o0), b0 = __ldg(Y1 + o0);
        float a1 = __ldg(Y0 + o1), b1 = __ldg(Y1 + o1);
        float a2 = __ldg(Y0 + o2), b2 = __ldg(Y1 + o2);
        float a3 = __ldg(Y0 + o3), b3 = __ldg(Y1 + o3);
        acc0 = fmaf(w0s[s + 0], a0, acc0); acc1 = fmaf(w1s[s + 0], b0, acc1);
        acc0 = fmaf(w0s[s + 1], a1, acc0); acc1 = fmaf(w1s[s + 1], b1, acc1);
        acc0 = fmaf(w0s[s + 2], a2, acc0); acc1 = fmaf(w1s[s + 2], b2, acc1);
        acc0 = fmaf(w0s[s + 3], a3, acc0); acc1 = fmaf(w1s[s + 3], b3, acc1);
    }
    for (; s < n1; s++) {
        int o = offs[s] + f;
        acc0 = fmaf(w0s[s], __ldg(Y0 + o), acc0);
        acc1 = fmaf(w1s[s], __ldg(Y1 + o), acc1);
    }

    int nd0 = min(dropn[0], MAXDROP);
    for (int d = 0; d < nd0; d++)
        acc0 -= droph[0][d] * g_XW[(size_t)dropj[0][d] * WOUT + f];
    int nd1 = min(dropn[1], MAXDROP);
    for (int d = 0; d < nd1; d++)
        acc1 -= droph[1][d] * g_XW[(size_t)dropj[1][d] * WOUT + f];

    float o0 = coef[0] * acc0 + bias;
    float o1 = coef[1] * acc1 + bias;
    out[(size_t)i * (NC * WOUT) + f]        = fmaxf(o0, 0.f);
    out[(size_t)i * (NC * WOUT) + WOUT + f] = fmaxf(o1, 0.f);
}

// ---------------------------------------------------------------------------
extern "C" void kernel_launch(void* const* d_in, const int* in_sizes, int n_in,
                              void* d_out, int out_size) {
    const float* A   = (const float*)d_in[0];
    const float* X   = (const float*)d_in[1];
    const float* W1a = (const float*)d_in[2];
    const float* W1b = (const float*)d_in[3];
    const float* Wg  = (const float*)d_in[4];
    const float* bg  = (const float*)d_in[5];
    float* out = (float*)d_out;

    void* nnz_ptr = nullptr;
    cudaGetSymbolAddress(&nnz_ptr, g_nnz);
    cudaMemsetAsync(nnz_ptr, 0, NN * sizeof(int));

    k_pre<<<GEMM_BLOCKS + 1, 256>>>(X, Wg, W1a, W1b);
    k_scan<<<SCAN_BLOCKS, 256>>>(A);
    k_y<<<NN, 256>>>();
    k_final<<<NN, 256>>>(bg, out);
}